// round 10
// baseline (speedup 1.0000x reference)
#include <cuda_runtime.h>

// Haar DWT2, single level.
// x: [8, 64, 512, 512] f32  ->  out: 4 subbands (ll, lh, hl, hh) concatenated,
// each [8, 64, 256, 256] f32.
//
// R2 per-tile structure (best measured: 157.7us wall / 150.3us kernel, DRAM=86%),
// converted to a PERSISTENT grid-stride kernel: exactly one wave of CTAs
// (148 SMs x 8 CTAs = 1184), each thread processes 28 tiles. This removes the
// 27 wave transitions of the 32768-CTA launch, keeping front-batched loads in
// flight continuously instead of re-ramping MLP on every CTA launch.
// (Resubmission of R6 kernel — previous bench failed on container infra.)

#define W_IN       512
#define SUBBAND_N  33554432u   // 512 * 256 * 256
#define TOTAL_QUADS 8388608u   // 512 * 256 * 64
#define GRID_CTAS  1184u       // 148 SMs * 8 resident CTAs

__global__ void __launch_bounds__(256, 8)
haar_dwt2_kernel(const float* __restrict__ x, float* __restrict__ out)
{
    const unsigned stride = GRID_CTAS * 256u;   // 303104 threads
    unsigned g = blockIdx.x * blockDim.x + threadIdx.x;

    #pragma unroll 1
    for (; g < TOTAL_QUADS; g += stride) {
        // g = ((bc * 256) + i) * 64 + q   (all powers of two -> shifts)
        unsigned q  = g & 63u;          // quad index along output width (j0 = 4*q)
        unsigned i  = (g >> 6) & 255u;  // output row
        unsigned bc = g >> 14;          // fused batch*channel index (0..511)

        // Input base: element ((bc*512 + 2*i) * 512 + 8*q)
        unsigned in_base = ((bc << 9) + (i << 1)) * (unsigned)W_IN + (q << 3);

        const float4* p0 = (const float4*)(x + in_base);            // row 2i
        const float4* p1 = (const float4*)(x + in_base + W_IN);     // row 2i+1

        // Front-batched independent loads (MLP = 4)
        float4 r0a = p0[0];
        float4 r0b = p0[1];
        float4 r1a = p1[0];
        float4 r1b = p1[1];

        // De-interleave: a = even cols row 2i, b = odd cols row 2i,
        //                c = even cols row 2i+1, d = odd cols row 2i+1
        float4 a = make_float4(r0a.x, r0a.z, r0b.x, r0b.z);
        float4 b = make_float4(r0a.y, r0a.w, r0b.y, r0b.w);
        float4 c = make_float4(r1a.x, r1a.z, r1b.x, r1b.z);
        float4 d = make_float4(r1a.y, r1a.w, r1b.y, r1b.w);

        const float s = 0.5f;

        float4 ll, lh, hl, hh;
        ll.x = (a.x + b.x + c.x + d.x) * s;
        ll.y = (a.y + b.y + c.y + d.y) * s;
        ll.z = (a.z + b.z + c.z + d.z) * s;
        ll.w = (a.w + b.w + c.w + d.w) * s;

        lh.x = (a.x + b.x - c.x - d.x) * s;
        lh.y = (a.y + b.y - c.y - d.y) * s;
        lh.z = (a.z + b.z - c.z - d.z) * s;
        lh.w = (a.w + b.w - c.w - d.w) * s;

        hl.x = (a.x - b.x + c.x - d.x) * s;
        hl.y = (a.y - b.y + c.y - d.y) * s;
        hl.z = (a.z - b.z + c.z - d.z) * s;
        hl.w = (a.w - b.w + c.w - d.w) * s;

        hh.x = (a.x - b.x - c.x + d.x) * s;
        hh.y = (a.y - b.y - c.y + d.y) * s;
        hh.z = (a.z - b.z - c.z + d.z) * s;
        hh.w = (a.w - b.w - c.w + d.w) * s;

        // Output element offset within a subband: ((bc*256 + i) * 256 + 4*q)
        unsigned out_off = (((bc << 8) + i) << 8) + (q << 2);

        __stcs((float4*)(out + out_off), ll);
        __stcs((float4*)(out + SUBBAND_N      + out_off), lh);
        __stcs((float4*)(out + 2u * SUBBAND_N + out_off), hl);
        __stcs((float4*)(out + 3u * SUBBAND_N + out_off), hh);
    }
}

extern "C" void kernel_launch(void* const* d_in, const int* in_sizes, int n_in,
                              void* d_out, int out_size)
{
    const float* x = (const float*)d_in[0];
    float* out = (float*)d_out;

    dim3 grid(GRID_CTAS);
    dim3 block(256);
    haar_dwt2_kernel<<<grid, block>>>(x, out);
}

// round 11
// speedup vs baseline: 1.1185x; 1.1185x over previous
#include <cuda_runtime.h>

// Haar DWT2, single level.
// x: [8, 64, 512, 512] f32  ->  out: 4 subbands (ll, lh, hl, hh) concatenated,
// each [8, 64, 256, 256] f32.
//
// Best-known structure (R2: 157.7us wall, 150.4us kernel, DRAM=86%):
// each thread reads a 2x8 input patch (4 front-batched float4 loads, 32 regs,
// full 2048-thread occupancy) and writes one float4 per subband (.cs stores).
// Delta this round: 128-thread CTAs (65536 blocks) for finer work-distributor
// granularity at identical warp-level addressing and occupancy budget.

#define W_IN       512
#define SUBBAND_N  33554432u  // 512 * 256 * 256

__global__ void __launch_bounds__(128, 16)
haar_dwt2_kernel(const float* __restrict__ x, float* __restrict__ out)
{
    unsigned tid = blockIdx.x * blockDim.x + threadIdx.x;

    // tid = ((bc * 256) + i) * 64 + q   (all powers of two -> shifts)
    unsigned q  = tid & 63u;          // quad index along output width (j0 = 4*q)
    unsigned i  = (tid >> 6) & 255u;  // output row
    unsigned bc = tid >> 14;          // fused batch*channel index (0..511)

    // Input base: element ((bc*512 + 2*i) * 512 + 8*q)
    unsigned in_base = ((bc << 9) + (i << 1)) * (unsigned)W_IN + (q << 3);

    const float4* p0 = (const float4*)(x + in_base);            // row 2i
    const float4* p1 = (const float4*)(x + in_base + W_IN);     // row 2i+1

    // Front-batched independent loads (MLP = 4), default cache policy
    float4 r0a = p0[0];
    float4 r0b = p0[1];
    float4 r1a = p1[0];
    float4 r1b = p1[1];

    // De-interleave columns: a = even cols (row 2i), b = odd cols (row 2i),
    //                        c = even cols (row 2i+1), d = odd cols (row 2i+1)
    float4 a = make_float4(r0a.x, r0a.z, r0b.x, r0b.z);
    float4 b = make_float4(r0a.y, r0a.w, r0b.y, r0b.w);
    float4 c = make_float4(r1a.x, r1a.z, r1b.x, r1b.z);
    float4 d = make_float4(r1a.y, r1a.w, r1b.y, r1b.w);

    const float s = 0.5f;

    float4 ll, lh, hl, hh;
    ll.x = (a.x + b.x + c.x + d.x) * s;
    ll.y = (a.y + b.y + c.y + d.y) * s;
    ll.z = (a.z + b.z + c.z + d.z) * s;
    ll.w = (a.w + b.w + c.w + d.w) * s;

    lh.x = (a.x + b.x - c.x - d.x) * s;
    lh.y = (a.y + b.y - c.y - d.y) * s;
    lh.z = (a.z + b.z - c.z - d.z) * s;
    lh.w = (a.w + b.w - c.w - d.w) * s;

    hl.x = (a.x - b.x + c.x - d.x) * s;
    hl.y = (a.y - b.y + c.y - d.y) * s;
    hl.z = (a.z - b.z + c.z - d.z) * s;
    hl.w = (a.w - b.w + c.w - d.w) * s;

    hh.x = (a.x - b.x - c.x + d.x) * s;
    hh.y = (a.y - b.y - c.y + d.y) * s;
    hh.z = (a.z - b.z - c.z + d.z) * s;
    hh.w = (a.w - b.w - c.w + d.w) * s;

    // Output element offset within a subband: ((bc*256 + i) * 256 + 4*q)
    unsigned out_off = (((bc << 8) + i) << 8) + (q << 2);

    __stcs((float4*)(out + out_off), ll);
    __stcs((float4*)(out + SUBBAND_N      + out_off), lh);
    __stcs((float4*)(out + 2u * SUBBAND_N + out_off), hl);
    __stcs((float4*)(out + 3u * SUBBAND_N + out_off), hh);
}

extern "C" void kernel_launch(void* const* d_in, const int* in_sizes, int n_in,
                              void* d_out, int out_size)
{
    const float* x = (const float*)d_in[0];
    float* out = (float*)d_out;

    // Total quads = 512 * 256 * 64 = 8,388,608 threads; 128 threads/block
    dim3 grid(8388608u / 128u);   // 65536 blocks
    dim3 block(128);
    haar_dwt2_kernel<<<grid, block>>>(x, out);
}

// round 12
// speedup vs baseline: 1.1197x; 1.0010x over previous
#include <cuda_runtime.h>

// Haar DWT2, single level.
// x: [8, 64, 512, 512] f32  ->  out: 4 subbands (ll, lh, hl, hh) concatenated,
// each [8, 64, 256, 256] f32.
//
// Best-known structure (R2/R5: 157.7us wall, 150.4us kernel, DRAM=85.5-86%):
// each thread reads a 2x8 input patch (4 front-batched float4 loads, 32 regs,
// occ-8 at 256 threads) and writes one float4 per subband.
// Final isolated delta: evict-first (.cs) on the loads as well as the stores —
// every byte is touched exactly once in both directions.

#define W_IN       512
#define SUBBAND_N  33554432u  // 512 * 256 * 256

__global__ void __launch_bounds__(256, 8)
haar_dwt2_kernel(const float* __restrict__ x, float* __restrict__ out)
{
    unsigned tid = blockIdx.x * blockDim.x + threadIdx.x;

    // tid = ((bc * 256) + i) * 64 + q   (all powers of two -> shifts)
    unsigned q  = tid & 63u;          // quad index along output width (j0 = 4*q)
    unsigned i  = (tid >> 6) & 255u;  // output row
    unsigned bc = tid >> 14;          // fused batch*channel index (0..511)

    // Input base: element ((bc*512 + 2*i) * 512 + 8*q)
    unsigned in_base = ((bc << 9) + (i << 1)) * (unsigned)W_IN + (q << 3);

    const float4* p0 = (const float4*)(x + in_base);            // row 2i
    const float4* p1 = (const float4*)(x + in_base + W_IN);     // row 2i+1

    // Front-batched independent loads (MLP = 4), streaming (evict-first) policy
    float4 r0a = __ldcs(p0 + 0);
    float4 r0b = __ldcs(p0 + 1);
    float4 r1a = __ldcs(p1 + 0);
    float4 r1b = __ldcs(p1 + 1);

    // De-interleave columns: a = even cols (row 2i), b = odd cols (row 2i),
    //                        c = even cols (row 2i+1), d = odd cols (row 2i+1)
    float4 a = make_float4(r0a.x, r0a.z, r0b.x, r0b.z);
    float4 b = make_float4(r0a.y, r0a.w, r0b.y, r0b.w);
    float4 c = make_float4(r1a.x, r1a.z, r1b.x, r1b.z);
    float4 d = make_float4(r1a.y, r1a.w, r1b.y, r1b.w);

    const float s = 0.5f;

    float4 ll, lh, hl, hh;
    ll.x = (a.x + b.x + c.x + d.x) * s;
    ll.y = (a.y + b.y + c.y + d.y) * s;
    ll.z = (a.z + b.z + c.z + d.z) * s;
    ll.w = (a.w + b.w + c.w + d.w) * s;

    lh.x = (a.x + b.x - c.x - d.x) * s;
    lh.y = (a.y + b.y - c.y - d.y) * s;
    lh.z = (a.z + b.z - c.z - d.z) * s;
    lh.w = (a.w + b.w - c.w - d.w) * s;

    hl.x = (a.x - b.x + c.x - d.x) * s;
    hl.y = (a.y - b.y + c.y - d.y) * s;
    hl.z = (a.z - b.z + c.z - d.z) * s;
    hl.w = (a.w - b.w + c.w - d.w) * s;

    hh.x = (a.x - b.x - c.x + d.x) * s;
    hh.y = (a.y - b.y - c.y + d.y) * s;
    hh.z = (a.z - b.z - c.z + d.z) * s;
    hh.w = (a.w - b.w - c.w + d.w) * s;

    // Output element offset within a subband: ((bc*256 + i) * 256 + 4*q)
    unsigned out_off = (((bc << 8) + i) << 8) + (q << 2);

    __stcs((float4*)(out + out_off), ll);
    __stcs((float4*)(out + SUBBAND_N      + out_off), lh);
    __stcs((float4*)(out + 2u * SUBBAND_N + out_off), hl);
    __stcs((float4*)(out + 3u * SUBBAND_N + out_off), hh);
}

extern "C" void kernel_launch(void* const* d_in, const int* in_sizes, int n_in,
                              void* d_out, int out_size)
{
    const float* x = (const float*)d_in[0];
    float* out = (float*)d_out;

    // Total quads = 512 * 256 * 64 = 8,388,608 threads; 256 threads/block
    dim3 grid(8388608u / 256u);   // 32768 blocks
    dim3 block(256);
    haar_dwt2_kernel<<<grid, block>>>(x, out);
}